// round 11
// baseline (speedup 1.0000x reference)
#include <cuda_runtime.h>
#include <cuda_bf16.h>
#include <mma.h>
#include <math.h>
#include <stdint.h>

#define NN      4096
#define NFEAT   512
#define NHID    64
#define NHEADS  8
#define NCLASS  41
#define HD      (NHEADS*NHID)   /* 512 */
#define MAXD    256
#define ALPHA   0.2f
#define KSPLIT  8

using namespace nvcuda;

/* scratch */
__device__ int   g_deg[NN];
__device__ int   g_nbr[NN*MAXD];
__device__ float g_Wh [NN*HD];
__device__ float g_s1 [NHEADS*NN];
__device__ float g_s2 [NHEADS*NN];
__device__ float g_h  [NN*HD];
__device__ float g_Wh2[NN*NCLASS];
__device__ float g_p1 [NN];
__device__ float g_p2 [NN];
__device__ float g_part[KSPLIT*NN*48];

/* ------------------------------------------------------------------ */
__device__ __forceinline__ void csr_chunk(float4 v, int jb, int row,
                                          int& base, unsigned lt) {
    unsigned m0 = __ballot_sync(0xffffffffu, v.x > 0.0f);
    unsigned m1 = __ballot_sync(0xffffffffu, v.y > 0.0f);
    unsigned m2 = __ballot_sync(0xffffffffu, v.z > 0.0f);
    unsigned m3 = __ballot_sync(0xffffffffu, v.w > 0.0f);
    int below = __popc(m0 & lt) + __popc(m1 & lt) +
                __popc(m2 & lt) + __popc(m3 & lt);
    int p = base + below;
    if (v.x > 0.0f) { if (p < MAXD) g_nbr[row * MAXD + p] = jb + 0; p++; }
    if (v.y > 0.0f) { if (p < MAXD) g_nbr[row * MAXD + p] = jb + 1; p++; }
    if (v.z > 0.0f) { if (p < MAXD) g_nbr[row * MAXD + p] = jb + 2; p++; }
    if (v.w > 0.0f) { if (p < MAXD) g_nbr[row * MAXD + p] = jb + 3; p++; }
    base += __popc(m0) + __popc(m1) + __popc(m2) + __popc(m3);
}

__device__ __forceinline__ void cvt4(float4 v, __nv_bfloat162& h0, __nv_bfloat162& h1,
                                     __nv_bfloat162& l0, __nv_bfloat162& l1) {
    h0.x = __float2bfloat16(v.x); h0.y = __float2bfloat16(v.y);
    h1.x = __float2bfloat16(v.z); h1.y = __float2bfloat16(v.w);
    l0.x = __float2bfloat16(v.x - __bfloat162float(h0.x));
    l0.y = __float2bfloat16(v.y - __bfloat162float(h0.y));
    l1.x = __float2bfloat16(v.z - __bfloat162float(h1.x));
    l1.y = __float2bfloat16(v.w - __bfloat162float(h1.y));
}

/* ------------------------------------------------------------------ */
/* fused1: blocks 0..511 -> double-buffered bf16-split wmma GEMM       */
/*         + fused s1/s2 epilogue. blocks 512..1023 -> CSR build.      */
__global__ void __launch_bounds__(256, 3)
fused1(const float* __restrict__ adj, const float* __restrict__ x,
       const float* __restrict__ Wv,  const float* __restrict__ a_heads) {
    const int bid = blockIdx.x, t = threadIdx.x;
    const int wid = t >> 5, lane = t & 31;

    if (bid >= 512) {
        /* ---- CSR build: warp per row, 4 independent loads per iter ---- */
        const int row = (bid - 512) * 8 + wid;
        const float4* arow = (const float4*)(adj + (size_t)row * NN);
        const unsigned lt = (1u << lane) - 1u;
        int base = 0;
#pragma unroll 2
        for (int j0 = 0; j0 < NN / 4; j0 += 128) {
            float4 v0 = arow[j0 +       lane];
            float4 v1 = arow[j0 +  32 + lane];
            float4 v2 = arow[j0 +  64 + lane];
            float4 v3 = arow[j0 +  96 + lane];
            csr_chunk(v0, (j0 +       lane) * 4, row, base, lt);
            csr_chunk(v1, (j0 +  32 + lane) * 4, row, base, lt);
            csr_chunk(v2, (j0 +  64 + lane) * 4, row, base, lt);
            csr_chunk(v3, (j0 +  96 + lane) * 4, row, base, lt);
        }
        if (lane == 0) g_deg[row] = base < MAXD ? base : MAXD;
        return;
    }

    /* ---- GEMM: block = 64 rows, one head; double-buffered smem ---- */
    __shared__ __nv_bfloat16 As_hi[2][64 * 24];
    __shared__ __nv_bfloat16 As_lo[2][64 * 24];
    __shared__ __nv_bfloat16 Bs_hi[2][16 * 72];
    __shared__ __nv_bfloat16 Bs_lo[2][16 * 72];
    __shared__ float         Cs[64 * 72];
    __shared__ float         s_a12[128];

    const int bm = (bid & 63) * 64;
    const int h  = bid >> 6;
    const int wm = wid & 3;
    const int wn = wid >> 2;
    const float* Wb = Wv + (size_t)h * NFEAT * NHID;

    if (t < 128) s_a12[t] = a_heads[h * 128 + t];

    wmma::fragment<wmma::matrix_a, 16, 16, 16, __nv_bfloat16, wmma::row_major> ah, al;
    wmma::fragment<wmma::matrix_b, 16, 16, 16, __nv_bfloat16, wmma::row_major> bh, bl;
    wmma::fragment<wmma::accumulator, 16, 16, 16, float> acc[2];
    wmma::fill_fragment(acc[0], 0.0f);
    wmma::fill_fragment(acc[1], 0.0f);

    const int ar = t >> 2, ac = (t & 3) * 4;
    const int bk = t >> 4, bn = (t & 15) * 4;

    /* prologue: stage K-chunk 0 into buffer 0 */
    {
        float4 av = *(const float4*)(x + (size_t)(bm + ar) * NFEAT + ac);
        float4 bv = *(const float4*)(Wb + (size_t)bk * NHID + bn);
        __nv_bfloat162 h0, h1, l0, l1;
        cvt4(av, h0, h1, l0, l1);
        *(__nv_bfloat162*)(As_hi[0] + ar * 24 + ac)     = h0;
        *(__nv_bfloat162*)(As_hi[0] + ar * 24 + ac + 2) = h1;
        *(__nv_bfloat162*)(As_lo[0] + ar * 24 + ac)     = l0;
        *(__nv_bfloat162*)(As_lo[0] + ar * 24 + ac + 2) = l1;
        cvt4(bv, h0, h1, l0, l1);
        *(__nv_bfloat162*)(Bs_hi[0] + bk * 72 + bn)     = h0;
        *(__nv_bfloat162*)(Bs_hi[0] + bk * 72 + bn + 2) = h1;
        *(__nv_bfloat162*)(Bs_lo[0] + bk * 72 + bn)     = l0;
        *(__nv_bfloat162*)(Bs_lo[0] + bk * 72 + bn + 2) = l1;
    }
    __syncthreads();

    for (int ks = 0; ks < 32; ks++) {
        const int cur = ks & 1, nxt = cur ^ 1;
        const bool have = (ks + 1 < 32);
        float4 av, bv;
        if (have) {
            const int kt = (ks + 1) * 16;
            av = *(const float4*)(x + (size_t)(bm + ar) * NFEAT + kt + ac);
            bv = *(const float4*)(Wb + (size_t)(kt + bk) * NHID + bn);
        }
        /* mma on cur buffer */
        wmma::load_matrix_sync(ah, As_hi[cur] + wm * 16 * 24, 24);
        wmma::load_matrix_sync(al, As_lo[cur] + wm * 16 * 24, 24);
#pragma unroll
        for (int f = 0; f < 2; f++) {
            wmma::load_matrix_sync(bh, Bs_hi[cur] + wn * 32 + f * 16, 72);
            wmma::load_matrix_sync(bl, Bs_lo[cur] + wn * 32 + f * 16, 72);
            wmma::mma_sync(acc[f], ah, bh, acc[f]);
            wmma::mma_sync(acc[f], ah, bl, acc[f]);
            wmma::mma_sync(acc[f], al, bh, acc[f]);
        }
        if (have) {
            __nv_bfloat162 h0, h1, l0, l1;
            cvt4(av, h0, h1, l0, l1);
            *(__nv_bfloat162*)(As_hi[nxt] + ar * 24 + ac)     = h0;
            *(__nv_bfloat162*)(As_hi[nxt] + ar * 24 + ac + 2) = h1;
            *(__nv_bfloat162*)(As_lo[nxt] + ar * 24 + ac)     = l0;
            *(__nv_bfloat162*)(As_lo[nxt] + ar * 24 + ac + 2) = l1;
            cvt4(bv, h0, h1, l0, l1);
            *(__nv_bfloat162*)(Bs_hi[nxt] + bk * 72 + bn)     = h0;
            *(__nv_bfloat162*)(Bs_hi[nxt] + bk * 72 + bn + 2) = h1;
            *(__nv_bfloat162*)(Bs_lo[nxt] + bk * 72 + bn)     = l0;
            *(__nv_bfloat162*)(Bs_lo[nxt] + bk * 72 + bn + 2) = l1;
        }
        __syncthreads();
    }

#pragma unroll
    for (int f = 0; f < 2; f++)
        wmma::store_matrix_sync(Cs + wm * 16 * 72 + wn * 32 + f * 16, acc[f],
                                72, wmma::mem_row_major);
    __syncthreads();

    if (t < 64) {
        float s1 = 0.0f, s2 = 0.0f;
        const float* row = Cs + t * 72;
#pragma unroll 16
        for (int c = 0; c < 64; c++) {
            float f = row[c];
            s1 += f * s_a12[c];
            s2 += f * s_a12[64 + c];
        }
        g_s1[h * NN + bm + t] = s1;
        g_s2[h * NN + bm + t] = s2;
    }
    for (int idx = t; idx < 64 * 64; idx += 256) {
        int rr = idx >> 6, cc = idx & 63;
        g_Wh[(size_t)(bm + rr) * HD + h * NHID + cc] = Cs[rr * 72 + cc];
    }
}

/* ------------------------------------------------------------------ */
/* layer-1 attention: warp per head; float4 gathers, 2 neighbors/iter  */
__global__ void attn1(void) {
    const int i = blockIdx.x, t = threadIdx.x;
    const int h = t >> 5, lane = t & 31;
    const int half = lane >> 4, cl = lane & 15;
    __shared__ int   nb[MAXD];
    __shared__ float ew[NHEADS][MAXD];

    const int deg = g_deg[i];
    if (t < deg) nb[t] = g_nbr[i * MAXD + t];
    __syncthreads();

    const float s1i = g_s1[h * NN + i];
    float ev[8];
    float m = -1e30f;
#pragma unroll
    for (int c = 0; c < 8; c++) {
        int k = c * 32 + lane;
        float e = -1e30f;
        if (k < deg) {
            e = s1i + g_s2[h * NN + nb[k]];
            e = e > 0.0f ? e : ALPHA * e;
        }
        ev[c] = e; m = fmaxf(m, e);
    }
#pragma unroll
    for (int o = 16; o; o >>= 1) m = fmaxf(m, __shfl_xor_sync(0xffffffffu, m, o));
    float s = 0.0f;
#pragma unroll
    for (int c = 0; c < 8; c++) {
        int k = c * 32 + lane;
        if (k < deg) { float x = __expf(ev[c] - m); ew[h][k] = x; s += x; }
    }
#pragma unroll
    for (int o = 16; o; o >>= 1) s += __shfl_xor_sync(0xffffffffu, s, o);
    const float inv = 1.0f / s;
    __syncwarp();

    /* aggregation: half-warp per neighbor, float4 per lane (4 cols) */
    const int hoff = h * NHID;
    float4 acc0 = {0, 0, 0, 0}, acc1 = {0, 0, 0, 0};
    int k = 0;
    for (; k + 4 <= deg; k += 4) {
        int ka = k + half, kb = k + 2 + half;
        float wa = ew[h][ka], wb = ew[h][kb];
        float4 va = ((const float4*)(g_Wh + (size_t)nb[ka] * HD + hoff))[cl];
        float4 vb = ((const float4*)(g_Wh + (size_t)nb[kb] * HD + hoff))[cl];
        acc0.x += wa * va.x; acc0.y += wa * va.y;
        acc0.z += wa * va.z; acc0.w += wa * va.w;
        acc1.x += wb * vb.x; acc1.y += wb * vb.y;
        acc1.z += wb * vb.z; acc1.w += wb * vb.w;
    }
    for (; k < deg; k += 2) {
        int kk = k + half;
        if (kk < deg) {
            float w0 = ew[h][kk];
            float4 v = ((const float4*)(g_Wh + (size_t)nb[kk] * HD + hoff))[cl];
            acc0.x += w0 * v.x; acc0.y += w0 * v.y;
            acc0.z += w0 * v.z; acc0.w += w0 * v.w;
        }
    }
    float4 acc;
    acc.x = acc0.x + acc1.x; acc.y = acc0.y + acc1.y;
    acc.z = acc0.z + acc1.z; acc.w = acc0.w + acc1.w;
    acc.x += __shfl_xor_sync(0xffffffffu, acc.x, 16);
    acc.y += __shfl_xor_sync(0xffffffffu, acc.y, 16);
    acc.z += __shfl_xor_sync(0xffffffffu, acc.z, 16);
    acc.w += __shfl_xor_sync(0xffffffffu, acc.w, 16);
    if (half == 0) {
        acc.x *= inv; acc.y *= inv; acc.z *= inv; acc.w *= inv;
        acc.x = acc.x > 0.0f ? acc.x : (__expf(acc.x) - 1.0f);
        acc.y = acc.y > 0.0f ? acc.y : (__expf(acc.y) - 1.0f);
        acc.z = acc.z > 0.0f ? acc.z : (__expf(acc.z) - 1.0f);
        acc.w = acc.w > 0.0f ? acc.w : (__expf(acc.w) - 1.0f);
        ((float4*)(g_h + (size_t)i * HD + hoff))[cl] = acc;
    }
}

/* ------------------------------------------------------------------ */
/* out_proj split-K: grid = 64 m-tiles x 8 k-slices; BM=64, BK=32,     */
/* 4x3 per-thread register tile                                        */
__global__ void out_proj_k(const float* __restrict__ W_out) {
    __shared__ float As[32][68];
    __shared__ float Bs[32][48];
    const int mt = blockIdx.x >> 3, ks = blockIdx.x & 7;
    const int t  = threadIdx.x;
    const int bm = mt * 64;
    const int k0 = ks * (HD / KSPLIT);
    const int tx = t & 15, ty = t >> 4;
    float acc[4][3] = {};

    for (int kt = k0; kt < k0 + HD / KSPLIT; kt += 32) {
        {
            int r  = t >> 3, c4 = (t & 7) * 4;
            float4 v0 = *(const float4*)(g_h + (size_t)(bm + r)      * HD + kt + c4);
            float4 v1 = *(const float4*)(g_h + (size_t)(bm + 32 + r) * HD + kt + c4);
            As[c4 + 0][r] = v0.x; As[c4 + 1][r] = v0.y;
            As[c4 + 2][r] = v0.z; As[c4 + 3][r] = v0.w;
            As[c4 + 0][32 + r] = v1.x; As[c4 + 1][32 + r] = v1.y;
            As[c4 + 2][32 + r] = v1.z; As[c4 + 3][32 + r] = v1.w;
        }
        for (int i = t; i < 32 * 48; i += 256) {
            int kk = i / 48, c = i - kk * 48;
            Bs[kk][c] = (c < NCLASS) ? W_out[(size_t)(kt + kk) * NCLASS + c] : 0.0f;
        }
        __syncthreads();
#pragma unroll 8
        for (int k = 0; k < 32; k++) {
            float a0 = As[k][ty * 4], a1 = As[k][ty * 4 + 1];
            float a2 = As[k][ty * 4 + 2], a3 = As[k][ty * 4 + 3];
            float b0 = Bs[k][tx * 3], b1 = Bs[k][tx * 3 + 1], b2 = Bs[k][tx * 3 + 2];
            acc[0][0] += a0 * b0; acc[0][1] += a0 * b1; acc[0][2] += a0 * b2;
            acc[1][0] += a1 * b0; acc[1][1] += a1 * b1; acc[1][2] += a1 * b2;
            acc[2][0] += a2 * b0; acc[2][1] += a2 * b1; acc[2][2] += a2 * b2;
            acc[3][0] += a3 * b0; acc[3][1] += a3 * b1; acc[3][2] += a3 * b2;
        }
        __syncthreads();
    }
    float* dst = g_part + ((size_t)ks * NN + bm) * 48;
#pragma unroll
    for (int i = 0; i < 4; i++)
#pragma unroll
        for (int j = 0; j < 3; j++)
            dst[(ty * 4 + i) * 48 + tx * 3 + j] = acc[i][j];
}

/* ------------------------------------------------------------------ */
/* reduce: warp per row — sum 8 partials, write Wh2, fused p1/p2       */
__global__ void reduce_k(const float* __restrict__ a_out) {
    const int w = threadIdx.x >> 5, lane = threadIdx.x & 31;
    const int row = blockIdx.x * 8 + w;
    float v1 = 0.0f, v2 = 0.0f;
    const int c1 = lane, c2 = lane + 32;
#pragma unroll
    for (int s = 0; s < KSPLIT; s++) {
        const float* p = g_part + ((size_t)s * NN + row) * 48;
        v1 += p[c1];
        if (c2 < NCLASS) v2 += p[c2];
    }
    float p1 = 0.0f, p2 = 0.0f;
    if (c1 < NCLASS) {
        g_Wh2[row * NCLASS + c1] = v1;
        p1 += v1 * a_out[c1];
        p2 += v1 * a_out[NCLASS + c1];
    }
    if (c2 < NCLASS) {
        g_Wh2[row * NCLASS + c2] = v2;
        p1 += v2 * a_out[c2];
        p2 += v2 * a_out[NCLASS + c2];
    }
#pragma unroll
    for (int o = 16; o; o >>= 1) {
        p1 += __shfl_down_sync(0xffffffffu, p1, o);
        p2 += __shfl_down_sync(0xffffffffu, p2, o);
    }
    if (lane == 0) { g_p1[row] = p1; g_p2[row] = p2; }
}

/* ------------------------------------------------------------------ */
/* layer-2 attention: warp per node, no block barriers                 */
__global__ void attn2(float* __restrict__ out) {
    __shared__ float sw [8][MAXD];
    __shared__ int   snb[8][MAXD];
    const int w = threadIdx.x >> 5, lane = threadIdx.x & 31;
    const int i = blockIdx.x * 8 + w;
    const int deg = g_deg[i];

    const float p1i = g_p1[i];
    float ev[8];
    float m = -1e30f;
#pragma unroll
    for (int c = 0; c < 8; c++) {
        int k = c * 32 + lane;
        float e = -1e30f;
        if (k < deg) {
            int j = g_nbr[i * MAXD + k];
            snb[w][k] = j;
            e = p1i + g_p2[j];
            e = e > 0.0f ? e : ALPHA * e;
        }
        ev[c] = e; m = fmaxf(m, e);
    }
#pragma unroll
    for (int o = 16; o; o >>= 1) m = fmaxf(m, __shfl_xor_sync(0xffffffffu, m, o));
    float s = 0.0f;
#pragma unroll
    for (int c = 0; c < 8; c++) {
        int k = c * 32 + lane;
        if (k < deg) { float x = __expf(ev[c] - m); sw[w][k] = x; s += x; }
    }
#pragma unroll
    for (int o = 16; o; o >>= 1) s += __shfl_xor_sync(0xffffffffu, s, o);
    const float inv = 1.0f / s;
    __syncwarp();

    const int c1 = lane, c2 = lane + 32;
    float o1 = -1e30f, o2 = -1e30f;
    {
        float a0 = 0, a1 = 0, b0 = 0, b1 = 0;
        int k = 0;
        for (; k + 2 <= deg; k += 2) {
            float w0 = sw[w][k], w1 = sw[w][k + 1];
            const float* r0 = g_Wh2 + (size_t)snb[w][k]     * NCLASS;
            const float* r1 = g_Wh2 + (size_t)snb[w][k + 1] * NCLASS;
            if (c1 < NCLASS) { a0 += w0 * r0[c1]; b0 += w1 * r1[c1]; }
            if (c2 < NCLASS) { a1 += w0 * r0[c2]; b1 += w1 * r1[c2]; }
        }
        if (k < deg) {
            float w0 = sw[w][k];
            const float* r0 = g_Wh2 + (size_t)snb[w][k] * NCLASS;
            if (c1 < NCLASS) a0 += w0 * r0[c1];
            if (c2 < NCLASS) a1 += w0 * r0[c2];
        }
        if (c1 < NCLASS) {
            float v = (a0 + b0) * inv;
            o1 = v > 0.0f ? v : (__expf(v) - 1.0f);
        }
        if (c2 < NCLASS) {
            float v = (a1 + b1) * inv;
            o2 = v > 0.0f ? v : (__expf(v) - 1.0f);
        }
    }
    float mx = fmaxf(o1, o2);
#pragma unroll
    for (int o = 16; o; o >>= 1) mx = fmaxf(mx, __shfl_xor_sync(0xffffffffu, mx, o));
    float ex = ((c1 < NCLASS) ? __expf(o1 - mx) : 0.0f)
             + ((c2 < NCLASS) ? __expf(o2 - mx) : 0.0f);
#pragma unroll
    for (int o = 16; o; o >>= 1) ex += __shfl_xor_sync(0xffffffffu, ex, o);
    const float lse = mx + __logf(ex);
    if (c1 < NCLASS) out[i * NCLASS + c1] = o1 - lse;
    if (c2 < NCLASS) out[i * NCLASS + c2] = o2 - lse;
}

/* ------------------------------------------------------------------ */
extern "C" void kernel_launch(void* const* d_in, const int* in_sizes, int n_in,
                              void* d_out, int out_size) {
    const float *x = 0, *adj = 0, *W_heads = 0, *a_heads = 0, *W_out = 0, *a_out = 0;
    for (int i = 0; i < n_in; i++) {
        switch (in_sizes[i]) {
            case NN*NFEAT:            x       = (const float*)d_in[i]; break;
            case NN*NN:               adj     = (const float*)d_in[i]; break;
            case NHEADS*NFEAT*NHID:   W_heads = (const float*)d_in[i]; break;
            case NHEADS*2*NHID:       a_heads = (const float*)d_in[i]; break;
            case HD*NCLASS:           W_out   = (const float*)d_in[i]; break;
            case 2*NCLASS:            a_out   = (const float*)d_in[i]; break;
        }
    }
    float* out = (float*)d_out;

    fused1    <<<1024, 256>>>(adj, x, W_heads, a_heads);
    attn1     <<<NN, 256>>>();
    out_proj_k<<<512, 256>>>(W_out);
    reduce_k  <<<NN / 8, 256>>>(a_out);
    attn2     <<<NN / 8, 256>>>(out);
}

// round 12
// speedup vs baseline: 1.0659x; 1.0659x over previous
#include <cuda_runtime.h>
#include <cuda_bf16.h>
#include <mma.h>
#include <math.h>
#include <stdint.h>

#define NN      4096
#define NFEAT   512
#define NHID    64
#define NHEADS  8
#define NCLASS  41
#define HD      (NHEADS*NHID)   /* 512 */
#define MAXD    256
#define ALPHA   0.2f
#define KSPLIT  8

using namespace nvcuda;

/* scratch */
__device__ int   g_deg[NN];
__device__ int   g_nbr[NN*MAXD];
__device__ float g_Wh [NN*HD];
__device__ float g_s1 [NHEADS*NN];
__device__ float g_s2 [NHEADS*NN];
__device__ float g_h  [NN*HD];
__device__ float g_Wh2[NN*NCLASS];
__device__ float g_p1 [NN];
__device__ float g_p2 [NN];
__device__ float g_part[KSPLIT*NN*48];

/* ------------------------------------------------------------------ */
__device__ __forceinline__ void csr_chunk(float4 v, int jb, int row,
                                          int& base, unsigned lt) {
    unsigned m0 = __ballot_sync(0xffffffffu, v.x > 0.0f);
    unsigned m1 = __ballot_sync(0xffffffffu, v.y > 0.0f);
    unsigned m2 = __ballot_sync(0xffffffffu, v.z > 0.0f);
    unsigned m3 = __ballot_sync(0xffffffffu, v.w > 0.0f);
    int below = __popc(m0 & lt) + __popc(m1 & lt) +
                __popc(m2 & lt) + __popc(m3 & lt);
    int p = base + below;
    if (v.x > 0.0f) { if (p < MAXD) g_nbr[row * MAXD + p] = jb + 0; p++; }
    if (v.y > 0.0f) { if (p < MAXD) g_nbr[row * MAXD + p] = jb + 1; p++; }
    if (v.z > 0.0f) { if (p < MAXD) g_nbr[row * MAXD + p] = jb + 2; p++; }
    if (v.w > 0.0f) { if (p < MAXD) g_nbr[row * MAXD + p] = jb + 3; p++; }
    base += __popc(m0) + __popc(m1) + __popc(m2) + __popc(m3);
}

__device__ __forceinline__ void cvt4(float4 v, __nv_bfloat162& h0, __nv_bfloat162& h1,
                                     __nv_bfloat162& l0, __nv_bfloat162& l1) {
    h0.x = __float2bfloat16(v.x); h0.y = __float2bfloat16(v.y);
    h1.x = __float2bfloat16(v.z); h1.y = __float2bfloat16(v.w);
    l0.x = __float2bfloat16(v.x - __bfloat162float(h0.x));
    l0.y = __float2bfloat16(v.y - __bfloat162float(h0.y));
    l1.x = __float2bfloat16(v.z - __bfloat162float(h1.x));
    l1.y = __float2bfloat16(v.w - __bfloat162float(h1.y));
}

/* ------------------------------------------------------------------ */
/* fused1: blocks 0..511 -> bf16-split wmma GEMM (Wh = x @ W_head)     */
/*         + fused s1/s2 epilogue. blocks 512..1023 -> CSR build       */
/*         (warp per row, 4-way MLP-unrolled scan).                    */
__global__ void __launch_bounds__(256, 4)
fused1(const float* __restrict__ adj, const float* __restrict__ x,
       const float* __restrict__ Wv,  const float* __restrict__ a_heads) {
    const int bid = blockIdx.x, t = threadIdx.x;
    const int wid = t >> 5, lane = t & 31;

    if (bid >= 512) {
        /* ---- CSR build: warp per row, 4 independent loads per iter ---- */
        const int row = (bid - 512) * 8 + wid;
        const float4* arow = (const float4*)(adj + (size_t)row * NN);
        const unsigned lt = (1u << lane) - 1u;
        int base = 0;
#pragma unroll 2
        for (int j0 = 0; j0 < NN / 4; j0 += 128) {
            float4 v0 = arow[j0 +       lane];
            float4 v1 = arow[j0 +  32 + lane];
            float4 v2 = arow[j0 +  64 + lane];
            float4 v3 = arow[j0 +  96 + lane];
            csr_chunk(v0, (j0 +       lane) * 4, row, base, lt);
            csr_chunk(v1, (j0 +  32 + lane) * 4, row, base, lt);
            csr_chunk(v2, (j0 +  64 + lane) * 4, row, base, lt);
            csr_chunk(v3, (j0 +  96 + lane) * 4, row, base, lt);
        }
        if (lane == 0) g_deg[row] = base < MAXD ? base : MAXD;
        return;
    }

    /* ---- GEMM: block = 64 rows of x, one head; 8 warps 4x2 ---- */
    __shared__ __nv_bfloat16 As_hi[64 * 24];
    __shared__ __nv_bfloat16 As_lo[64 * 24];
    __shared__ __nv_bfloat16 Bs_hi[16 * 72];
    __shared__ __nv_bfloat16 Bs_lo[16 * 72];
    __shared__ float         Cs[64 * 72];
    __shared__ float         s_a12[128];

    const int bm = (bid & 63) * 64;
    const int h  = bid >> 6;
    const int wm = wid & 3;
    const int wn = wid >> 2;
    const float* Wb = Wv + (size_t)h * NFEAT * NHID;

    if (t < 128) s_a12[t] = a_heads[h * 128 + t];

    wmma::fragment<wmma::matrix_a, 16, 16, 16, __nv_bfloat16, wmma::row_major> ah, al;
    wmma::fragment<wmma::matrix_b, 16, 16, 16, __nv_bfloat16, wmma::row_major> bh, bl;
    wmma::fragment<wmma::accumulator, 16, 16, 16, float> acc[2];
    wmma::fill_fragment(acc[0], 0.0f);
    wmma::fill_fragment(acc[1], 0.0f);

    const int ar = t >> 2, ac = (t & 3) * 4;
    const int bk = t >> 4, bn = (t & 15) * 4;

    for (int kt = 0; kt < NFEAT; kt += 16) {
        float4 av = *(const float4*)(x + (size_t)(bm + ar) * NFEAT + kt + ac);
        float4 bv = *(const float4*)(Wb + (size_t)(kt + bk) * NHID + bn);
        {
            __nv_bfloat162 h0, h1, l0, l1;
            cvt4(av, h0, h1, l0, l1);
            *(__nv_bfloat162*)(As_hi + ar * 24 + ac)     = h0;
            *(__nv_bfloat162*)(As_hi + ar * 24 + ac + 2) = h1;
            *(__nv_bfloat162*)(As_lo + ar * 24 + ac)     = l0;
            *(__nv_bfloat162*)(As_lo + ar * 24 + ac + 2) = l1;
        }
        {
            __nv_bfloat162 h0, h1, l0, l1;
            cvt4(bv, h0, h1, l0, l1);
            *(__nv_bfloat162*)(Bs_hi + bk * 72 + bn)     = h0;
            *(__nv_bfloat162*)(Bs_hi + bk * 72 + bn + 2) = h1;
            *(__nv_bfloat162*)(Bs_lo + bk * 72 + bn)     = l0;
            *(__nv_bfloat162*)(Bs_lo + bk * 72 + bn + 2) = l1;
        }
        __syncthreads();

        wmma::load_matrix_sync(ah, As_hi + wm * 16 * 24, 24);
        wmma::load_matrix_sync(al, As_lo + wm * 16 * 24, 24);
#pragma unroll
        for (int f = 0; f < 2; f++) {
            wmma::load_matrix_sync(bh, Bs_hi + wn * 32 + f * 16, 72);
            wmma::load_matrix_sync(bl, Bs_lo + wn * 32 + f * 16, 72);
            wmma::mma_sync(acc[f], ah, bh, acc[f]);
            wmma::mma_sync(acc[f], ah, bl, acc[f]);
            wmma::mma_sync(acc[f], al, bh, acc[f]);
        }
        __syncthreads();
    }

#pragma unroll
    for (int f = 0; f < 2; f++)
        wmma::store_matrix_sync(Cs + wm * 16 * 72 + wn * 32 + f * 16, acc[f],
                                72, wmma::mem_row_major);
    __syncthreads();

    if (t < 64) {
        float s1 = 0.0f, s2 = 0.0f;
        const float* row = Cs + t * 72;
#pragma unroll 16
        for (int c = 0; c < 64; c++) {
            float f = row[c];
            s1 += f * s_a12[c];
            s2 += f * s_a12[64 + c];
        }
        g_s1[h * NN + bm + t] = s1;
        g_s2[h * NN + bm + t] = s2;
    }
    for (int idx = t; idx < 64 * 64; idx += 256) {
        int rr = idx >> 6, cc = idx & 63;
        g_Wh[(size_t)(bm + rr) * HD + h * NHID + cc] = Cs[rr * 72 + cc];
    }
}

/* ------------------------------------------------------------------ */
/* layer-1 attention: block per node, warp per head, shuffle softmax   */
__global__ void attn1(void) {
    const int i = blockIdx.x, t = threadIdx.x;
    const int h = t >> 5, lane = t & 31;
    __shared__ int   nb[MAXD];
    __shared__ float ew[NHEADS][MAXD];

    const int deg = g_deg[i];
    if (t < deg) nb[t] = g_nbr[i * MAXD + t];
    __syncthreads();

    const float s1i = g_s1[h * NN + i];
    float ev[8];
    float m = -1e30f;
#pragma unroll
    for (int c = 0; c < 8; c++) {
        int k = c * 32 + lane;
        float e = -1e30f;
        if (k < deg) {
            e = s1i + g_s2[h * NN + nb[k]];
            e = e > 0.0f ? e : ALPHA * e;
        }
        ev[c] = e; m = fmaxf(m, e);
    }
#pragma unroll
    for (int o = 16; o; o >>= 1) m = fmaxf(m, __shfl_xor_sync(0xffffffffu, m, o));
    float s = 0.0f;
#pragma unroll
    for (int c = 0; c < 8; c++) {
        int k = c * 32 + lane;
        if (k < deg) { float x = __expf(ev[c] - m); ew[h][k] = x; s += x; }
    }
#pragma unroll
    for (int o = 16; o; o >>= 1) s += __shfl_xor_sync(0xffffffffu, s, o);
    const float inv = 1.0f / s;
    __syncwarp();

    const int hoff = h * NHID;
    float a0 = 0, a1 = 0, b0 = 0, b1 = 0, c0 = 0, c1 = 0, d0 = 0, d1 = 0;
    int k = 0;
    for (; k + 4 <= deg; k += 4) {
        float w0 = ew[h][k], w1 = ew[h][k + 1], w2 = ew[h][k + 2], w3 = ew[h][k + 3];
        const float* r0 = g_Wh + (size_t)nb[k]     * HD + hoff;
        const float* r1 = g_Wh + (size_t)nb[k + 1] * HD + hoff;
        const float* r2 = g_Wh + (size_t)nb[k + 2] * HD + hoff;
        const float* r3 = g_Wh + (size_t)nb[k + 3] * HD + hoff;
        a0 += w0 * r0[lane]; a1 += w0 * r0[lane + 32];
        b0 += w1 * r1[lane]; b1 += w1 * r1[lane + 32];
        c0 += w2 * r2[lane]; c1 += w2 * r2[lane + 32];
        d0 += w3 * r3[lane]; d1 += w3 * r3[lane + 32];
    }
    for (; k < deg; k++) {
        float w0 = ew[h][k];
        const float* r0 = g_Wh + (size_t)nb[k] * HD + hoff;
        a0 += w0 * r0[lane]; a1 += w0 * r0[lane + 32];
    }
    float v0 = (a0 + b0 + c0 + d0) * inv;
    float v1 = (a1 + b1 + c1 + d1) * inv;
    v0 = v0 > 0.0f ? v0 : (__expf(v0) - 1.0f);
    v1 = v1 > 0.0f ? v1 : (__expf(v1) - 1.0f);
    g_h[(size_t)i * HD + hoff + lane]      = v0;
    g_h[(size_t)i * HD + hoff + lane + 32] = v1;
}

/* ------------------------------------------------------------------ */
/* out_proj: bf16-split wmma GEMM, grid = 64 m-tiles x 8 k-slices      */
/* BM=64, BN=64 (48 used), K-slice 64 = 4 x K16 iters                  */
__global__ void __launch_bounds__(256)
out_proj_k(const float* __restrict__ W_out) {
    __shared__ __nv_bfloat16 As_hi[64 * 24];
    __shared__ __nv_bfloat16 As_lo[64 * 24];
    __shared__ __nv_bfloat16 Bs_hi[16 * 72];
    __shared__ __nv_bfloat16 Bs_lo[16 * 72];
    __shared__ float         Cs[64 * 72];

    const int mt = blockIdx.x >> 3, ks = blockIdx.x & 7;
    const int t  = threadIdx.x;
    const int wid = t >> 5;
    const int bm = mt * 64;
    const int k0 = ks * (HD / KSPLIT);   /* 64-wide K slice */
    const int wm = wid & 3, wn = wid >> 2;

    wmma::fragment<wmma::matrix_a, 16, 16, 16, __nv_bfloat16, wmma::row_major> ah, al;
    wmma::fragment<wmma::matrix_b, 16, 16, 16, __nv_bfloat16, wmma::row_major> bh, bl;
    wmma::fragment<wmma::accumulator, 16, 16, 16, float> acc[2];
    wmma::fill_fragment(acc[0], 0.0f);
    wmma::fill_fragment(acc[1], 0.0f);

    const int ar = t >> 2, ac = (t & 3) * 4;   /* A: 64x16 fp32, float4/thread */
    const int bk = t >> 4, bn = (t & 15) * 4;  /* B: 16x64 padded              */

    for (int kt = k0; kt < k0 + HD / KSPLIT; kt += 16) {
        float4 av = *(const float4*)(g_h + (size_t)(bm + ar) * HD + kt + ac);
        {
            __nv_bfloat162 h0, h1, l0, l1;
            cvt4(av, h0, h1, l0, l1);
            *(__nv_bfloat162*)(As_hi + ar * 24 + ac)     = h0;
            *(__nv_bfloat162*)(As_hi + ar * 24 + ac + 2) = h1;
            *(__nv_bfloat162*)(As_lo + ar * 24 + ac)     = l0;
            *(__nv_bfloat162*)(As_lo + ar * 24 + ac + 2) = l1;
        }
        {
            const float* wr = W_out + (size_t)(kt + bk) * NCLASS;
            float4 bv;
            bv.x = (bn     < NCLASS) ? wr[bn]     : 0.0f;
            bv.y = (bn + 1 < NCLASS) ? wr[bn + 1] : 0.0f;
            bv.z = (bn + 2 < NCLASS) ? wr[bn + 2] : 0.0f;
            bv.w = (bn + 3 < NCLASS) ? wr[bn + 3] : 0.0f;
            __nv_bfloat162 h0, h1, l0, l1;
            cvt4(bv, h0, h1, l0, l1);
            *(__nv_bfloat162*)(Bs_hi + bk * 72 + bn)     = h0;
            *(__nv_bfloat162*)(Bs_hi + bk * 72 + bn + 2) = h1;
            *(__nv_bfloat162*)(Bs_lo + bk * 72 + bn)     = l0;
            *(__nv_bfloat162*)(Bs_lo + bk * 72 + bn + 2) = l1;
        }
        __syncthreads();

        wmma::load_matrix_sync(ah, As_hi + wm * 16 * 24, 24);
        wmma::load_matrix_sync(al, As_lo + wm * 16 * 24, 24);
#pragma unroll
        for (int f = 0; f < 2; f++) {
            wmma::load_matrix_sync(bh, Bs_hi + wn * 32 + f * 16, 72);
            wmma::load_matrix_sync(bl, Bs_lo + wn * 32 + f * 16, 72);
            wmma::mma_sync(acc[f], ah, bh, acc[f]);
            wmma::mma_sync(acc[f], ah, bl, acc[f]);
            wmma::mma_sync(acc[f], al, bh, acc[f]);
        }
        __syncthreads();
    }

#pragma unroll
    for (int f = 0; f < 2; f++)
        wmma::store_matrix_sync(Cs + wm * 16 * 72 + wn * 32 + f * 16, acc[f],
                                72, wmma::mem_row_major);
    __syncthreads();
    float* dst = g_part + ((size_t)ks * NN + bm) * 48;
    for (int idx = t; idx < 64 * 48; idx += 256) {
        int r = idx / 48, c = idx - r * 48;
        dst[r * 48 + c] = Cs[r * 72 + c];
    }
}

/* ------------------------------------------------------------------ */
/* reduce: warp per row — sum 8 partials, write Wh2, fused p1/p2       */
__global__ void reduce_k(const float* __restrict__ a_out) {
    const int w = threadIdx.x >> 5, lane = threadIdx.x & 31;
    const int row = blockIdx.x * 8 + w;
    float v1 = 0.0f, v2 = 0.0f;
    const int c1 = lane, c2 = lane + 32;
#pragma unroll
    for (int s = 0; s < KSPLIT; s++) {
        const float* p = g_part + ((size_t)s * NN + row) * 48;
        v1 += p[c1];
        if (c2 < NCLASS) v2 += p[c2];
    }
    float p1 = 0.0f, p2 = 0.0f;
    if (c1 < NCLASS) {
        g_Wh2[row * NCLASS + c1] = v1;
        p1 += v1 * a_out[c1];
        p2 += v1 * a_out[NCLASS + c1];
    }
    if (c2 < NCLASS) {
        g_Wh2[row * NCLASS + c2] = v2;
        p1 += v2 * a_out[c2];
        p2 += v2 * a_out[NCLASS + c2];
    }
#pragma unroll
    for (int o = 16; o; o >>= 1) {
        p1 += __shfl_down_sync(0xffffffffu, p1, o);
        p2 += __shfl_down_sync(0xffffffffu, p2, o);
    }
    if (lane == 0) { g_p1[row] = p1; g_p2[row] = p2; }
}

/* ------------------------------------------------------------------ */
/* layer-2 attention: warp per node, no block barriers                 */
__global__ void attn2(float* __restrict__ out) {
    __shared__ float sw [8][MAXD];
    __shared__ int   snb[8][MAXD];
    const int w = threadIdx.x >> 5, lane = threadIdx.x & 31;
    const int i = blockIdx.x * 8 + w;
    const int deg = g_deg[i];

    const float p1i = g_p1[i];
    float ev[8];
    float m = -1e30f;
#pragma unroll
    for (int c = 0; c < 8; c++) {
        int k = c * 32 + lane;
        float e = -1e30f;
        if (k < deg) {
            int j = g_nbr[i * MAXD + k];
            snb[w][k] = j;
            e = p1i + g_p2[j];
            e = e > 0.0f ? e : ALPHA * e;
        }
        ev[c] = e; m = fmaxf(m, e);
    }
#pragma unroll
    for (int o = 16; o; o >>= 1) m = fmaxf(m, __shfl_xor_sync(0xffffffffu, m, o));
    float s = 0.0f;
#pragma unroll
    for (int c = 0; c < 8; c++) {
        int k = c * 32 + lane;
        if (k < deg) { float x = __expf(ev[c] - m); sw[w][k] = x; s += x; }
    }
#pragma unroll
    for (int o = 16; o; o >>= 1) s += __shfl_xor_sync(0xffffffffu, s, o);
    const float inv = 1.0f / s;
    __syncwarp();

    const int c1 = lane, c2 = lane + 32;
    float o1 = -1e30f, o2 = -1e30f;
    {
        float a0 = 0, a1 = 0, b0 = 0, b1 = 0;
        int k = 0;
        for (; k + 2 <= deg; k += 2) {
            float w0 = sw[w][k], w1 = sw[w][k + 1];
            const float* r0 = g_Wh2 + (size_t)snb[w][k]     * NCLASS;
            const float* r1 = g_Wh2 + (size_t)snb[w][k + 1] * NCLASS;
            if (c1 < NCLASS) { a0 += w0 * r0[c1]; b0 += w1 * r1[c1]; }
            if (c2 < NCLASS) { a1 += w0 * r0[c2]; b1 += w1 * r1[c2]; }
        }
        if (k < deg) {
            float w0 = sw[w][k];
            const float* r0 = g_Wh2 + (size_t)snb[w][k] * NCLASS;
            if (c1 < NCLASS) a0 += w0 * r0[c1];
            if (c2 < NCLASS) a1 += w0 * r0[c2];
        }
        if (c1 < NCLASS) {
            float v = (a0 + b0) * inv;
            o1 = v > 0.0f ? v : (__expf(v) - 1.0f);
        }
        if (c2 < NCLASS) {
            float v = (a1 + b1) * inv;
            o2 = v > 0.0f ? v : (__expf(v) - 1.0f);
        }
    }
    float mx = fmaxf(o1, o2);
#pragma unroll
    for (int o = 16; o; o >>= 1) mx = fmaxf(mx, __shfl_xor_sync(0xffffffffu, mx, o));
    float ex = ((c1 < NCLASS) ? __expf(o1 - mx) : 0.0f)
             + ((c2 < NCLASS) ? __expf(o2 - mx) : 0.0f);
#pragma unroll
    for (int o = 16; o; o >>= 1) ex += __shfl_xor_sync(0xffffffffu, ex, o);
    const float lse = mx + __logf(ex);
    if (c1 < NCLASS) out[i * NCLASS + c1] = o1 - lse;
    if (c2 < NCLASS) out[i * NCLASS + c2] = o2 - lse;
}

/* ------------------------------------------------------------------ */
extern "C" void kernel_launch(void* const* d_in, const int* in_sizes, int n_in,
                              void* d_out, int out_size) {
    const float *x = 0, *adj = 0, *W_heads = 0, *a_heads = 0, *W_out = 0, *a_out = 0;
    for (int i = 0; i < n_in; i++) {
        switch (in_sizes[i]) {
            case NN*NFEAT:            x       = (const float*)d_in[i]; break;
            case NN*NN:               adj     = (const float*)d_in[i]; break;
            case NHEADS*NFEAT*NHID:   W_heads = (const float*)d_in[i]; break;
            case NHEADS*2*NHID:       a_heads = (const float*)d_in[i]; break;
            case HD*NCLASS:           W_out   = (const float*)d_in[i]; break;
            case 2*NCLASS:            a_out   = (const float*)d_in[i]; break;
        }
    }
    float* out = (float*)d_out;

    fused1    <<<1024, 256>>>(adj, x, W_heads, a_heads);
    attn1     <<<NN, 256>>>();
    out_proj_k<<<512, 256>>>(W_out);
    reduce_k  <<<NN / 8, 256>>>(a_out);
    attn2     <<<NN / 8, 256>>>(out);
}